// round 12
// baseline (speedup 1.0000x reference)
#include <cuda_runtime.h>
#include <math.h>

// WaterNetModel: chunk-parallel scan, fused persistent kernel.
// Round 12: global barriers replaced by acyclic per-chunk watermark counters
// (chunk-0 blocks stream A->C->E with zero waits; phases overlap). s_start
// kept in registers across C->E (g_sstart eliminated). Base = round-10
// geometry: C16=16 (14x68 + 2x72), CA=32, 1024 blocks x 128 threads.
// Snow: s' = max(s + a, b) (max-plus, composable); A = Psum - melt*Tsum.
// Bucket: h' = c1*(h + xin), constant c1 (affine, composable).
// Outputs: Q [NT,NS] | H [NT,NS,NH] | S [NT,NS,NH].

#define NT 1096
#define NS 2048
#define NH 16
#define C16 16
#define CA 32
#define LANES (NS * NH)        // 32768
#define L4    (LANES / 4)      // 8192
#define NTHREADS (C16 * L4)    // 131072
#define BLK 128
#define NBLOCKS (NTHREADS / BLK)  // 1024 (<= 7*148 = 1036 resident at 64 regs)

// scratch
__device__ float g_Ps[CA * NS];          // per-A-chunk sum of pneg
__device__ float g_Ts[CA * NS];          // per-A-chunk sum of tpos
__device__ float g_B[CA * LANES];        // snow compose floor
__device__ float g_D[C16 * LANES];       // bucket chunk offsets

// watermark counters (reset by last block each launch -> replay-deterministic)
__device__ int g_ca_done[CA];            // 32 producing blocks per A-chunk
__device__ int g_d_done[C16];            // 64 producing blocks per C-chunk
__device__ int g_fin;

// C-chunk geometry: chunks 0..13 len 68, chunks 14..15 len 72
__device__ __forceinline__ int c_t0(int c)  { return (c < 14) ? 68 * c : 952 + 72 * (c - 14); }
__device__ __forceinline__ int c_len(int c) { return (c < 14) ? 68 : 72; }

__global__ __launch_bounds__(BLK, 7)
void waternet_fused(const float* __restrict__ P, const float* __restrict__ T,
                    const float* __restrict__ w_i, const float* __restrict__ w_o,
                    const float* __restrict__ w_l, const float* __restrict__ w_s,
                    float* __restrict__ Q, float* __restrict__ H,
                    float* __restrict__ S)
{
    // smem slabs: phase A uses [lenA<=36][64 sites]; phases C/E use [len<=72][32 sites]
    __shared__ float smP[2560];
    __shared__ float smT[2560];

    const int tid = threadIdx.x;
    const int g   = blockIdx.x * BLK + tid;   // [0, NTHREADS)

    // =============== Phase A: snow composition (half-site, 8 buckets) ====
    {
        const int caA  = g >> 12;              // A-chunk [0,32), uniform per block
        const int s0A  = ((blockIdx.x * BLK) & 4095) >> 1;
        const int slA  = tid >> 1;             // local site [0,64)
        const int half = tid & 1;
        const int b0A  = half * 8;

        const int c16A = caA >> 1;
        const int lenA = (caA & 1) ? ((c16A < 14) ? 32 : 36) : 36;
        const int t0A  = c_t0(c16A) + ((caA & 1) ? 36 : 0);

        for (int e = tid; e < lenA * 64; e += BLK) {
            const int t = e >> 6, j = e & 63;
            smP[e] = __ldg(P + (t0A + t) * NS + s0A + j);
            smT[e] = __ldg(T + (t0A + t) * NS + s0A + j);
        }

        float nm[8];                           // -melt
        #pragma unroll
        for (int j = 0; j < 8; j++) nm[j] = -(expf(w_s[b0A + j]) + 1.0f);

        __syncthreads();

        float B[8];
        #pragma unroll
        for (int j = 0; j < 8; j++) B[j] = -INFINITY;
        float Ps = 0.0f, Ts = 0.0f;

        #pragma unroll 4
        for (int k = 0; k < lenA; k++) {
            const float Tk = smT[k * 64 + slA];
            const float Pk = smP[k * 64 + slA];
            const float tpos = fmaxf(Tk, 0.0f);
            const float pneg = (Tk < 0.0f) ? Pk : 0.0f;
            Ps += pneg;
            Ts += tpos;
            #pragma unroll
            for (int j = 0; j < 8; j++) {
                const float a = fmaf(tpos, nm[j], pneg);
                B[j] = fmaxf(B[j] + a, pneg);
            }
        }

        const int siteA = s0A + slA;
        float4* dB = (float4*)&g_B[caA * LANES + siteA * NH + b0A];
        dB[0] = make_float4(B[0], B[1], B[2], B[3]);
        dB[1] = make_float4(B[4], B[5], B[6], B[7]);
        if (half == 0) {
            g_Ps[caA * NS + siteA] = Ps;
            g_Ts[caA * NS + siteA] = Ts;
        }

        // publish A-chunk completion
        __syncthreads();
        if (tid == 0) {
            __threadfence();
            atomicAdd(&g_ca_done[caA], 1);
        }
    }

    // ---- common decode for phases C and E (quad threads) ----
    const int lane4 = g & (L4 - 1);
    const int chunk = g >> 13;
    const int site  = lane4 >> 2;
    const int bg    = tid & 3;                 // == lane4 & 3
    const int b0    = bg * 4;
    const int sl    = tid >> 2;                // local site [0,32)

    const int t0  = c_t0(chunk);
    const int len = c_len(chunk);
    const int nG  = len >> 2;

    float s_sav[4];                            // s_start, carried C -> E in regs

    // =============== Phase C: stage slab, fold s_start, replay, write S ==
    {
        // stage this chunk's 32-site slab (reused by phase E!)
        const int s0 = ((blockIdx.x * BLK) & (L4 - 1)) >> 2;
        for (int e = tid; e < len * 32; e += BLK) {
            const int t = e >> 5, j = e & 31;
            smP[e] = __ldg(P + (t0 + t) * NS + s0 + j);
            smT[e] = __ldg(T + (t0 + t) * NS + s0 + j);
        }

        float melt[4], c1[4], cg[4];
        #pragma unroll
        for (int j = 0; j < 4; j++) {
            melt[j] = expf(w_s[b0 + j]) + 1.0f;
            const float gi = 1.0f / (1.0f + expf(-w_i[b0 + j]));
            c1[j] = 1.0f - 1.0f / (1.0f + expf(-w_l[b0 + j]));
            cg[j] = c1[j] * gi;
        }

        // wait for needed A-chunks (tid 0 polls; staging LDGs already in flight)
        const int nca = chunk * 2;
        if (tid == 0) {
            for (int ca = 0; ca < nca; ca++)
                while (((volatile int*)g_ca_done)[ca] < 32) __nanosleep(64);
            __threadfence();
        }
        __syncthreads();   // staging sync + acquire broadcast

        // distributed s_start fold
        float s[4] = {0, 0, 0, 0};
        #pragma unroll 2
        for (int ca = 0; ca < nca; ca++) {
            const float Ps = g_Ps[ca * NS + site];
            const float Ts = g_Ts[ca * NS + site];
            const float4 B = ((const float4*)g_B)[ca * L4 + lane4];
            s[0] = fmaxf(s[0] + fmaf(-melt[0], Ts, Ps), B.x);
            s[1] = fmaxf(s[1] + fmaf(-melt[1], Ts, Ps), B.y);
            s[2] = fmaxf(s[2] + fmaf(-melt[2], Ts, Ps), B.z);
            s[3] = fmaxf(s[3] + fmaf(-melt[3], Ts, Ps), B.w);
        }
        #pragma unroll
        for (int j = 0; j < 4; j++) s_sav[j] = s[j];

        float D[4] = {0, 0, 0, 0};
        float4* S4 = (float4*)S + (size_t)t0 * L4 + lane4;

        for (int g0 = 0; g0 < nG; g0++) {
            #pragma unroll
            for (int u = 0; u < 4; u++) {
                const int k = g0 * 4 + u;
                const float Tk = smT[k * 32 + sl];
                const float Pk = smP[k * 32 + sl];
                const float tpos = fmaxf(Tk, 0.0f);
                const float pneg = (Tk < 0.0f) ? Pk : 0.0f;
                const float ppos = (Tk > 0.0f) ? Pk : 0.0f;
                float sn[4];
                #pragma unroll
                for (int j = 0; j < 4; j++) {
                    const float sm = tpos * melt[j];
                    const float m  = fminf(sm, s[j]);
                    sn[j] = (s[j] - m) + pneg;
                    D[j] = fmaf(c1[j], D[j], cg[j] * (ppos + m));
                    s[j] = sn[j];
                }
                __stcs(&S4[(size_t)k * L4], make_float4(sn[0], sn[1], sn[2], sn[3]));
            }
        }
        ((float4*)g_D)[chunk * L4 + lane4] = make_float4(D[0], D[1], D[2], D[3]);

        // publish C-chunk D completion
        __syncthreads();
        if (tid == 0) {
            __threadfence();
            atomicAdd(&g_d_done[chunk], 1);
        }
    }

    // =============== Phase E: reuse smem slab, replay, write H and Q =====
    {
        float melt[4], gi[4], c1[4], glaw[4];
        {
            float mx = w_o[0];
            #pragma unroll
            for (int j = 1; j < NH; j++) mx = fmaxf(mx, w_o[j]);
            float ssum = 0.0f;
            #pragma unroll
            for (int j = 0; j < NH; j++) ssum += expf(w_o[j] - mx);
            #pragma unroll
            for (int j = 0; j < 4; j++) {
                melt[j] = expf(w_s[b0 + j]) + 1.0f;
                gi[j]   = 1.0f / (1.0f + expf(-w_i[b0 + j]));
                const float gl = 1.0f / (1.0f + expf(-w_l[b0 + j]));
                c1[j]   = 1.0f - gl;
                glaw[j] = gl * (expf(w_o[b0 + j] - mx) / ssum);
            }
        }

        // wait for previous chunks' D (chunk 0 never waits)
        if (tid == 0) {
            for (int k = 0; k < chunk; k++)
                while (((volatile int*)g_d_done)[k] < 64) __nanosleep(64);
            __threadfence();
        }
        __syncthreads();

        // h_start: fold over previous chunks' D (len-dependent decay)
        float hh[4] = {0, 0, 0, 0};
        {
            float c68[4], c72[4];
            #pragma unroll
            for (int j = 0; j < 4; j++) {
                const float x2  = c1[j] * c1[j];
                const float x4  = x2 * x2;
                const float x8  = x4 * x4;
                const float x16 = x8 * x8;
                const float x32 = x16 * x16;
                const float x64 = x32 * x32;
                c68[j] = x64 * x4;
                c72[j] = c68[j] * x4;
            }
            #pragma unroll 2
            for (int k = 0; k < chunk; k++) {
                const float4 D = ((const float4*)g_D)[k * L4 + lane4];
                const bool big = (k >= 14);
                hh[0] = (big ? c72[0] : c68[0]) * hh[0] + D.x;
                hh[1] = (big ? c72[1] : c68[1]) * hh[1] + D.y;
                hh[2] = (big ? c72[2] : c68[2]) * hh[2] + D.z;
                hh[3] = (big ? c72[3] : c68[3]) * hh[3] + D.w;
            }
        }

        float s[4] = {s_sav[0], s_sav[1], s_sav[2], s_sav[3]};
        float4* H4 = (float4*)H + (size_t)t0 * L4 + lane4;

        for (int g0 = 0; g0 < nG; g0++) {
            #pragma unroll
            for (int u = 0; u < 4; u++) {
                const int k = g0 * 4 + u;
                const float Tk = smT[k * 32 + sl];
                const float Pk = smP[k * 32 + sl];
                const float tpos = fmaxf(Tk, 0.0f);
                const float pneg = (Tk < 0.0f) ? Pk : 0.0f;
                const float ppos = (Tk > 0.0f) ? Pk : 0.0f;
                float hn[4];
                float qa = 0.0f;
                #pragma unroll
                for (int j = 0; j < 4; j++) {
                    const float sm  = tpos * melt[j];
                    const float m   = fminf(sm, s[j]);
                    s[j] = (s[j] - m) + pneg;
                    const float u2  = fmaf(ppos + m, gi[j], hh[j]);
                    hn[j] = c1[j] * u2;            // h - q + xin
                    hh[j] = hn[j];
                    qa = fmaf(u2, glaw[j], qa);    // q*a = u2*gl*a
                }
                __stcs(&H4[(size_t)k * L4], make_float4(hn[0], hn[1], hn[2], hn[3]));

                qa += __shfl_xor_sync(0xFFFFFFFFu, qa, 1);
                qa += __shfl_xor_sync(0xFFFFFFFFu, qa, 2);
                if (bg == 0) __stcs(&Q[(t0 + k) * NS + site], qa);
            }
        }
    }

    // =============== Finish: last block resets counters for next replay ==
    __syncthreads();
    if (tid == 0) {
        __threadfence();
        const int old = atomicAdd(&g_fin, 1);
        if (old == NBLOCKS - 1) {
            #pragma unroll
            for (int i = 0; i < CA; i++) g_ca_done[i] = 0;
            #pragma unroll
            for (int i = 0; i < C16; i++) g_d_done[i] = 0;
            __threadfence();
            g_fin = 0;
        }
    }
}

extern "C" void kernel_launch(void* const* d_in, const int* in_sizes, int n_in,
                              void* d_out, int out_size)
{
    const float* P   = (const float*)d_in[0];
    const float* T   = (const float*)d_in[1];
    const float* w_i = (const float*)d_in[2];
    const float* w_o = (const float*)d_in[3];
    const float* w_l = (const float*)d_in[4];
    const float* w_s = (const float*)d_in[5];

    float* Q = (float*)d_out;
    float* H = Q + (size_t)NT * NS;
    float* S = H + (size_t)NT * NS * NH;

    waternet_fused<<<NBLOCKS, BLK>>>(P, T, w_i, w_o, w_l, w_s, Q, H, S);
}

// round 13
// speedup vs baseline: 1.4024x; 1.4024x over previous
#include <cuda_runtime.h>
#include <math.h>

// WaterNetModel: chunk-parallel scan, fused persistent kernel.
// Round 13: single smem slab per block. Each block computes the A-summaries
// of ITS OWN chunk's two halves over its 32 sites from the already-staged
// C slab (A-work tiles exactly: 64 blocks/chunk x 32 sites). Phase A's
// separate 18MB global re-read + slab + sync are gone. Otherwise R10 config:
// C16=16 (14x68+2x72), 1024 blocks x 128 thr, gen-counter grid barrier x2.
// Snow: s' = max(s + a, b) (max-plus); A = Psum - melt*Tsum.
// Bucket: h' = c1*(h + xin), constant c1 (affine).
// Outputs: Q [NT,NS] | H [NT,NS,NH] | S [NT,NS,NH].

#define NT 1096
#define NS 2048
#define NH 16
#define C16 16
#define CA 32
#define LANES (NS * NH)        // 32768
#define L4    (LANES / 4)      // 8192
#define NTHREADS (C16 * L4)    // 131072
#define BLK 128
#define NBLOCKS (NTHREADS / BLK)  // 1024 (<= 8*148 = 1184 resident slots)

// scratch
__device__ float g_Ps[CA * NS];          // per-A-chunk sum of pneg
__device__ float g_Ts[CA * NS];          // per-A-chunk sum of tpos
__device__ float g_B[CA * LANES];        // snow compose floor
__device__ float g_sstart[C16 * LANES];  // C-chunk start snow state (C -> E)
__device__ float g_D[C16 * LANES];       // bucket chunk offsets

__device__ unsigned g_bar = 0;
__device__ unsigned g_gen = 0;

__device__ __forceinline__ void grid_sync()
{
    __syncthreads();
    if (threadIdx.x == 0) {
        __threadfence();
        unsigned gen = *(volatile unsigned*)&g_gen;
        unsigned arr = atomicAdd(&g_bar, 1u);
        if (arr == (unsigned)gridDim.x - 1u) {
            g_bar = 0;
            __threadfence();
            *(volatile unsigned*)&g_gen = gen + 1u;
        } else {
            while (*(volatile unsigned*)&g_gen == gen) { __nanosleep(32); }
        }
        __threadfence();
    }
    __syncthreads();
}

// C-chunk geometry: chunks 0..13 len 68, chunks 14..15 len 72
__device__ __forceinline__ int c_t0(int c)  { return (c < 14) ? 68 * c : 952 + 72 * (c - 14); }
__device__ __forceinline__ int c_len(int c) { return (c < 14) ? 68 : 72; }

__global__ __launch_bounds__(BLK, 8)
void waternet_fused(const float* __restrict__ P, const float* __restrict__ T,
                    const float* __restrict__ w_i, const float* __restrict__ w_o,
                    const float* __restrict__ w_l, const float* __restrict__ w_s,
                    float* __restrict__ Q, float* __restrict__ H,
                    float* __restrict__ S)
{
    // one slab per block: [len<=72][32 sites], used by phases A, C, E
    __shared__ float smP[2304];
    __shared__ float smT[2304];

    const int tid = threadIdx.x;
    const int g   = blockIdx.x * BLK + tid;   // [0, NTHREADS)

    const int lane4 = g & (L4 - 1);
    const int chunk = g >> 13;
    const int site  = lane4 >> 2;
    const int bg    = tid & 3;
    const int b0    = bg * 4;
    const int sl    = tid >> 2;                // local site [0,32)

    const int t0  = c_t0(chunk);
    const int len = c_len(chunk);
    const int nG  = len >> 2;

    // =============== Stage slab (once; reused by A, C, E) ================
    {
        const int s0 = ((blockIdx.x * BLK) & (L4 - 1)) >> 2;
        for (int e = tid; e < len * 32; e += BLK) {
            const int t = e >> 5, j = e & 31;
            smP[e] = __ldg(P + (t0 + t) * NS + s0 + j);
            smT[e] = __ldg(T + (t0 + t) * NS + s0 + j);
        }
    }

    float melt[4];
    #pragma unroll
    for (int j = 0; j < 4; j++) melt[j] = expf(w_s[b0 + j]) + 1.0f;

    __syncthreads();

    // =============== Phase A: own chunk's two half-summaries =============
    {
        // halves: [0,36) and [36,len)
        #pragma unroll
        for (int hlf = 0; hlf < 2; hlf++) {
            const int k0 = hlf ? 36 : 0;
            const int k1 = hlf ? len : 36;
            float B[4] = {-INFINITY, -INFINITY, -INFINITY, -INFINITY};
            float Ps = 0.0f, Ts = 0.0f;
            #pragma unroll 4
            for (int k = k0; k < k1; k++) {
                const float Tk = smT[k * 32 + sl];
                const float Pk = smP[k * 32 + sl];
                const float tpos = fmaxf(Tk, 0.0f);
                const float pneg = (Tk < 0.0f) ? Pk : 0.0f;
                Ps += pneg;
                Ts += tpos;
                #pragma unroll
                for (int j = 0; j < 4; j++) {
                    const float a = fmaf(tpos, -melt[j], pneg);
                    B[j] = fmaxf(B[j] + a, pneg);
                }
            }
            const int ca = 2 * chunk + hlf;
            ((float4*)g_B)[ca * L4 + lane4] = make_float4(B[0], B[1], B[2], B[3]);
            if (bg == 0) {
                g_Ps[ca * NS + site] = Ps;
                g_Ts[ca * NS + site] = Ts;
            }
        }
    }
    grid_sync();

    // =============== Phase C: fold s_start, replay snow, write S =========
    {
        float c1[4], cg[4];
        #pragma unroll
        for (int j = 0; j < 4; j++) {
            const float gi = 1.0f / (1.0f + expf(-w_i[b0 + j]));
            c1[j] = 1.0f - 1.0f / (1.0f + expf(-w_l[b0 + j]));
            cg[j] = c1[j] * gi;
        }

        // distributed s_start fold over preceding A-chunks
        float s[4] = {0, 0, 0, 0};
        {
            const int nca = chunk * 2;
            #pragma unroll 2
            for (int ca = 0; ca < nca; ca++) {
                const float Ps = g_Ps[ca * NS + site];
                const float Ts = g_Ts[ca * NS + site];
                const float4 B = ((const float4*)g_B)[ca * L4 + lane4];
                s[0] = fmaxf(s[0] + fmaf(-melt[0], Ts, Ps), B.x);
                s[1] = fmaxf(s[1] + fmaf(-melt[1], Ts, Ps), B.y);
                s[2] = fmaxf(s[2] + fmaf(-melt[2], Ts, Ps), B.z);
                s[3] = fmaxf(s[3] + fmaf(-melt[3], Ts, Ps), B.w);
            }
        }
        ((float4*)g_sstart)[chunk * L4 + lane4] = make_float4(s[0], s[1], s[2], s[3]);

        float D[4] = {0, 0, 0, 0};
        float4* S4 = (float4*)S + (size_t)t0 * L4 + lane4;

        for (int g0 = 0; g0 < nG; g0++) {
            #pragma unroll
            for (int u = 0; u < 4; u++) {
                const int k = g0 * 4 + u;
                const float Tk = smT[k * 32 + sl];
                const float Pk = smP[k * 32 + sl];
                const float tpos = fmaxf(Tk, 0.0f);
                const float pneg = (Tk < 0.0f) ? Pk : 0.0f;
                const float ppos = (Tk > 0.0f) ? Pk : 0.0f;
                float sn[4];
                #pragma unroll
                for (int j = 0; j < 4; j++) {
                    const float sm = tpos * melt[j];
                    const float m  = fminf(sm, s[j]);
                    sn[j] = (s[j] - m) + pneg;
                    D[j] = fmaf(c1[j], D[j], cg[j] * (ppos + m));
                    s[j] = sn[j];
                }
                __stcs(&S4[(size_t)k * L4], make_float4(sn[0], sn[1], sn[2], sn[3]));
            }
        }
        ((float4*)g_D)[chunk * L4 + lane4] = make_float4(D[0], D[1], D[2], D[3]);
    }
    grid_sync();

    // =============== Phase E: h_start fold, replay, write H and Q ========
    {
        float gi[4], c1[4], glaw[4];
        {
            float mx = w_o[0];
            #pragma unroll
            for (int j = 1; j < NH; j++) mx = fmaxf(mx, w_o[j]);
            float ssum = 0.0f;
            #pragma unroll
            for (int j = 0; j < NH; j++) ssum += expf(w_o[j] - mx);
            #pragma unroll
            for (int j = 0; j < 4; j++) {
                gi[j]   = 1.0f / (1.0f + expf(-w_i[b0 + j]));
                const float gl = 1.0f / (1.0f + expf(-w_l[b0 + j]));
                c1[j]   = 1.0f - gl;
                glaw[j] = gl * (expf(w_o[b0 + j] - mx) / ssum);
            }
        }

        // h_start: fold over previous chunks' D (len-dependent decay)
        float hh[4] = {0, 0, 0, 0};
        {
            float c68[4], c72[4];
            #pragma unroll
            for (int j = 0; j < 4; j++) {
                const float x2  = c1[j] * c1[j];
                const float x4  = x2 * x2;
                const float x8  = x4 * x4;
                const float x16 = x8 * x8;
                const float x32 = x16 * x16;
                const float x64 = x32 * x32;
                c68[j] = x64 * x4;
                c72[j] = c68[j] * x4;
            }
            #pragma unroll 2
            for (int k = 0; k < chunk; k++) {
                const float4 D = ((const float4*)g_D)[k * L4 + lane4];
                const bool big = (k >= 14);
                hh[0] = (big ? c72[0] : c68[0]) * hh[0] + D.x;
                hh[1] = (big ? c72[1] : c68[1]) * hh[1] + D.y;
                hh[2] = (big ? c72[2] : c68[2]) * hh[2] + D.z;
                hh[3] = (big ? c72[3] : c68[3]) * hh[3] + D.w;
            }
        }

        const float4 s0v = ((const float4*)g_sstart)[chunk * L4 + lane4];
        float s[4] = {s0v.x, s0v.y, s0v.z, s0v.w};
        float4* H4 = (float4*)H + (size_t)t0 * L4 + lane4;

        for (int g0 = 0; g0 < nG; g0++) {
            #pragma unroll
            for (int u = 0; u < 4; u++) {
                const int k = g0 * 4 + u;
                const float Tk = smT[k * 32 + sl];
                const float Pk = smP[k * 32 + sl];
                const float tpos = fmaxf(Tk, 0.0f);
                const float pneg = (Tk < 0.0f) ? Pk : 0.0f;
                const float ppos = (Tk > 0.0f) ? Pk : 0.0f;
                float hn[4];
                float qa = 0.0f;
                #pragma unroll
                for (int j = 0; j < 4; j++) {
                    const float sm  = tpos * melt[j];
                    const float m   = fminf(sm, s[j]);
                    s[j] = (s[j] - m) + pneg;
                    const float u2  = fmaf(ppos + m, gi[j], hh[j]);
                    hn[j] = c1[j] * u2;            // h - q + xin
                    hh[j] = hn[j];
                    qa = fmaf(u2, glaw[j], qa);    // q*a = u2*gl*a
                }
                __stcs(&H4[(size_t)k * L4], make_float4(hn[0], hn[1], hn[2], hn[3]));

                qa += __shfl_xor_sync(0xFFFFFFFFu, qa, 1);
                qa += __shfl_xor_sync(0xFFFFFFFFu, qa, 2);
                if (bg == 0) __stcs(&Q[(t0 + k) * NS + site], qa);
            }
        }
    }
}

extern "C" void kernel_launch(void* const* d_in, const int* in_sizes, int n_in,
                              void* d_out, int out_size)
{
    const float* P   = (const float*)d_in[0];
    const float* T   = (const float*)d_in[1];
    const float* w_i = (const float*)d_in[2];
    const float* w_o = (const float*)d_in[3];
    const float* w_l = (const float*)d_in[4];
    const float* w_s = (const float*)d_in[5];

    float* Q = (float*)d_out;
    float* H = Q + (size_t)NT * NS;
    float* S = H + (size_t)NT * NS * NH;

    waternet_fused<<<NBLOCKS, BLK>>>(P, T, w_i, w_o, w_l, w_s, Q, H, S);
}